// round 4
// baseline (speedup 1.0000x reference)
#include <cuda_runtime.h>
#include <math.h>

#define BDIM 256
#define SDIM 28
#define EDIM 256
#define ODIM 256
#define NBS  (BDIM*SDIM)          // 7168
#define NBSS (BDIM*SDIM*SDIM)     // 200704

// ---------------- scratch (device globals; no allocation allowed) -------------
__device__ float g_mask[NBS];
__device__ float g_u[NBS*EDIM];
__device__ float g_olfA[NBS*EDIM];
__device__ float g_olfB[NBS*EDIM];
__device__ float g_Ai[NBS*ODIM];
__device__ float g_Aj[NBS*ODIM];
__device__ float g_zx[NBS*4*ODIM];
__device__ float g_h0[BDIM*ODIM];
__device__ float g_h1[BDIM*ODIM];
__device__ float g_c[BDIM*ODIM];
__device__ float g_rlf[(size_t)NBSS*EDIM];   // 205 MB
__device__ float g_lin[(size_t)NBSS*ODIM];   // 205 MB
__device__ float g_gs[NBSS];
__device__ float g_M1[NBS*ODIM];
__device__ float g_D [NBS*ODIM];
__device__ float g_Mg[NBS];
__device__ float g_Dg[NBS];

// ---------------- prep: mask, u = (centers*mask)@Wr.T, olf0 -------------------
__global__ void k_prep(const float* __restrict__ centers, const float* __restrict__ emb,
                       const int* __restrict__ counts, const float* __restrict__ Wr) {
    int bs = blockIdx.x;           // b*S+s
    int e  = threadIdx.x;
    int b = bs / SDIM, s = bs % SDIM;
    float m = (s < counts[b]) ? 1.f : 0.f;
    if (e == 0) g_mask[bs] = m;
    float cx = centers[bs*3+0]*m, cy = centers[bs*3+1]*m, cz = centers[bs*3+2]*m;
    g_u[bs*EDIM+e]    = cx*Wr[e*3+0] + cy*Wr[e*3+1] + cz*Wr[e*3+2];
    g_olfA[bs*EDIM+e] = emb[bs*EDIM+e]*m;
}

// rlf0[b,i,j,e] = u[b,i,e] - u[b,j,e] + br[e]
__global__ void k_rlf0(const float* __restrict__ br) {
    int blk = blockIdx.x;          // (b*S+i)*S + j
    int e = threadIdx.x;
    int bi = blk / SDIM;
    int j  = blk % SDIM;
    int b  = blk / (SDIM*SDIM);
    g_rlf[(size_t)blk*EDIM + e] = g_u[bi*EDIM+e] - g_u[(b*SDIM+j)*EDIM+e] + br[e];
}

// ---------------- generic fp32 SGEMM:  C = A @ W^T  (W is [N,K]-slice) --------
// EPI 0: store  1: +p1[col]  2: +p1[bi,col]+p2[jrow,col]+p3[col]
// EPI 3: bezier/tanh/mask epilogue (A re-read as the lin matrix, N==K==256)
#define BM 128
#define BN 128
#define BK 8

template<int EPI>
__global__ void sgemm128(const float* __restrict__ A, const float* __restrict__ W,
                         int ldb, int woff, float* __restrict__ C, int N, int K,
                         const float* __restrict__ p1, const float* __restrict__ p2,
                         const float* __restrict__ p3, const float* __restrict__ alpha_p,
                         const float* __restrict__ maskp) {
    __shared__ float As[BK][BM];
    __shared__ float Bs[BK][BN];
    int bm = blockIdx.x * BM;
    int bn = blockIdx.y * BN;
    int tid = threadIdx.x;                // 256 threads
    int lr = tid >> 1;                    // 0..127
    int lc = (tid & 1) * 4;               // 0 or 4
    int tx = tid & 15, ty = tid >> 4;
    int rm = ty * 8, rn = tx * 8;
    float acc[8][8];
    #pragma unroll
    for (int i = 0; i < 8; i++)
        #pragma unroll
        for (int j = 0; j < 8; j++) acc[i][j] = 0.f;

    for (int k0 = 0; k0 < K; k0 += BK) {
        float4 av = *(const float4*)&A[(size_t)(bm+lr)*K + k0 + lc];
        float4 bv = *(const float4*)&W[(size_t)(bn+lr)*ldb + woff + k0 + lc];
        As[lc+0][lr]=av.x; As[lc+1][lr]=av.y; As[lc+2][lr]=av.z; As[lc+3][lr]=av.w;
        Bs[lc+0][lr]=bv.x; Bs[lc+1][lr]=bv.y; Bs[lc+2][lr]=bv.z; Bs[lc+3][lr]=bv.w;
        __syncthreads();
        #pragma unroll
        for (int k = 0; k < BK; k++) {
            float4 a0 = *(const float4*)&As[k][rm];
            float4 a1 = *(const float4*)&As[k][rm+4];
            float4 b0 = *(const float4*)&Bs[k][rn];
            float4 b1 = *(const float4*)&Bs[k][rn+4];
            float a[8] = {a0.x,a0.y,a0.z,a0.w,a1.x,a1.y,a1.z,a1.w};
            float bb[8] = {b0.x,b0.y,b0.z,b0.w,b1.x,b1.y,b1.z,b1.w};
            #pragma unroll
            for (int i = 0; i < 8; i++)
                #pragma unroll
                for (int j = 0; j < 8; j++) acc[i][j] += a[i]*bb[j];
        }
        __syncthreads();
    }

    float c0 = 0.f, c1 = 0.f;
    if (EPI == 3) {
        float t = 1.f/(1.f + expf(-(*alpha_p)));
        c0 = (1.f-t)*(1.f-t) + t*t;
        c1 = 2.f*(1.f-t)*t;
    }
    #pragma unroll
    for (int i = 0; i < 8; i++) {
        int mrow = bm + rm + i;
        int bi = 0, jrow = 0; float mprod = 0.f;
        if (EPI == 2 || EPI == 3) {
            bi = mrow / SDIM;
            int b  = mrow / (SDIM*SDIM);
            int jj = mrow % SDIM;
            jrow = b*SDIM + jj;
        }
        if (EPI == 3) mprod = maskp[bi]*maskp[jrow];
        #pragma unroll
        for (int j = 0; j < 8; j++) {
            int col = bn + rn + j;
            float v = acc[i][j];
            if (EPI == 1) v += p1[col];
            if (EPI == 2) v += p1[bi*ODIM+col] + p2[jrow*ODIM+col] + p3[col];
            if (EPI == 3) {
                float lv = A[(size_t)mrow*K + col];   // rlf_lin
                float cp = v + p3[col];               // + bbc
                v = tanhf(c0*lv + c1*cp) * mprod;
            }
            C[(size_t)mrow*N + col] = v;
        }
    }
}

// ---------------- LSTM recurrent step ----------------------------------------
// grid (8 unit-tiles, 8 batch-tiles), 256 thr. thread = (lane=batch, wid->4 units)
__global__ void k_lstm_step(const float* __restrict__ zx, int step,
                            const float* __restrict__ Whh,
                            const float* __restrict__ bih, const float* __restrict__ bhh,
                            float* __restrict__ newolf,
                            const float* __restrict__ hin, float* __restrict__ hout,
                            int first) {
    __shared__ float sh[256][33];
    int tid = threadIdx.x;
    int u0 = blockIdx.x * 32;
    int b0 = blockIdx.y * 32;
    int lane = tid & 31, wid = tid >> 5;
    float acc[4][4];
    #pragma unroll
    for (int q=0;q<4;q++)
        #pragma unroll
        for (int g=0;g<4;g++) acc[q][g]=0.f;

    if (!first) {
        for (int m = 0; m < 32; m++) {
            int idx = m*256 + tid; int bl = idx >> 8, k = idx & 255;
            sh[k][bl] = hin[(b0+bl)*ODIM + k];
        }
        __syncthreads();
        int ub = u0 + wid*4;
        for (int k = 0; k < 256; k += 4) {
            float h0=sh[k][lane], h1=sh[k+1][lane], h2=sh[k+2][lane], h3=sh[k+3][lane];
            #pragma unroll
            for (int q=0;q<4;q++) {
                int u = ub + q;
                #pragma unroll
                for (int g=0; g<4; g++) {
                    const float4 w = *(const float4*)&Whh[(size_t)(g*ODIM+u)*ODIM + k];
                    acc[q][g] += w.x*h0 + w.y*h1 + w.z*h2 + w.w*h3;
                }
            }
        }
    }
    int b = b0 + lane;
    int zbase = (b*SDIM + step)*4*ODIM;
    float mk = g_mask[b*SDIM + step];
    #pragma unroll
    for (int q=0;q<4;q++) {
        int u = u0 + wid*4 + q;
        float zi = acc[q][0] + zx[zbase +          u] + bih[         u] + bhh[         u];
        float zf = acc[q][1] + zx[zbase + ODIM   + u] + bih[ODIM   + u] + bhh[ODIM   + u];
        float zg = acc[q][2] + zx[zbase + 2*ODIM + u] + bih[2*ODIM + u] + bhh[2*ODIM + u];
        float zo = acc[q][3] + zx[zbase + 3*ODIM + u] + bih[3*ODIM + u] + bhh[3*ODIM + u];
        float cold = first ? 0.f : g_c[b*ODIM+u];
        float si = 1.f/(1.f+expf(-zi));
        float sf = 1.f/(1.f+expf(-zf));
        float so = 1.f/(1.f+expf(-zo));
        float cn = sf*cold + si*tanhf(zg);
        float hn = so*tanhf(cn);
        g_c[b*ODIM+u] = cn;
        hout[b*ODIM+u] = hn;
        newolf[(b*SDIM+step)*ODIM + u] = hn*mk;
    }
}

// ---------------- attention readout -------------------------------------------
// per (b,j,o): max_i / sum_i exp over F
__global__ void k_redF() {
    int bj = blockIdx.x;               // b*S + j
    int b = bj / SDIM, j = bj % SDIM;
    int o = threadIdx.x;
    float fv[SDIM];
    float m1 = -1e30f;
    #pragma unroll
    for (int i = 0; i < SDIM; i++) {
        fv[i] = g_lin[((size_t)(b*SDIM+i)*SDIM + j)*ODIM + o];
        m1 = fmaxf(m1, fv[i]);
    }
    float d = 0.f;
    #pragma unroll
    for (int i = 0; i < SDIM; i++) d += expf(fv[i]-m1);
    g_M1[bj*ODIM+o] = m1;
    g_D [bj*ODIM+o] = d;
}

// gs[b,i,j] = mean_r( F . Wmu[r] + bmu[r] )
__global__ void k_gs(const float* __restrict__ Wmu, const float* __restrict__ bmu) {
    int bi = blockIdx.x;               // b*S + i
    int tid = threadIdx.x;
    int lane = tid & 31, w = tid >> 5;
    float wb[8];
    #pragma unroll
    for (int m = 0; m < 8; m++) {
        int o = lane + 32*m;
        wb[m] = (Wmu[o] + Wmu[ODIM+o] + Wmu[2*ODIM+o]) * (1.f/3.f);
    }
    float bbar = (bmu[0]+bmu[1]+bmu[2]) * (1.f/3.f);
    for (int j = w; j < SDIM; j += 8) {
        const float* F = &g_lin[((size_t)bi*SDIM + j)*ODIM];
        float p = 0.f;
        #pragma unroll
        for (int m = 0; m < 8; m++) p += F[lane + 32*m]*wb[m];
        #pragma unroll
        for (int off = 16; off; off >>= 1) p += __shfl_down_sync(0xffffffffu, p, off);
        if (lane == 0) g_gs[bi*SDIM + j] = p + bbar;
    }
}

__global__ void k_redG() {
    int b = blockIdx.x; int j = threadIdx.x;
    if (j >= SDIM) return;
    float vals[SDIM]; float m = -1e30f;
    #pragma unroll
    for (int i = 0; i < SDIM; i++) { vals[i] = g_gs[(b*SDIM+i)*SDIM+j]; m = fmaxf(m, vals[i]); }
    float d = 0.f;
    #pragma unroll
    for (int i = 0; i < SDIM; i++) d += expf(vals[i]-m);
    g_Mg[b*SDIM+j] = m;
    g_Dg[b*SDIM+j] = d;
}

__global__ void k_final(float* __restrict__ out) {
    int bi = blockIdx.x;               // b*S + i
    int o = threadIdx.x;
    int b = bi / SDIM;
    float acc = 0.f;
    for (int j = 0; j < SDIM; j++) {
        float fv = g_lin[((size_t)bi*SDIM + j)*ODIM + o];
        int bj = b*SDIM + j;
        float a1 = expf(fv - g_M1[bj*ODIM+o]) / g_D[bj*ODIM+o];
        float ag = expf(g_gs[bi*SDIM+j] - g_Mg[bj]) / g_Dg[bj];
        acc += 0.5f*(a1 + ag)*fv;
    }
    out[bi*ODIM+o] = acc * g_mask[bi];
}

// ---------------- host ---------------------------------------------------------
extern "C" void kernel_launch(void* const* d_in, const int* in_sizes, int n_in,
                              void* d_out, int out_size) {
    const float* centers = (const float*)d_in[0];
    const float* emb     = (const float*)d_in[1];
    const int*   counts  = (const int*)  d_in[2];
    const float* Wr      = (const float*)d_in[3];
    const float* br      = (const float*)d_in[4];
    const float* W_ih    = (const float*)d_in[5];
    const float* W_hh    = (const float*)d_in[6];
    const float* b_ih    = (const float*)d_in[7];
    const float* b_hh    = (const float*)d_in[8];
    const float* Wgr     = (const float*)d_in[9];
    const float* bgr     = (const float*)d_in[10];
    const float* Wbc     = (const float*)d_in[11];
    const float* bbc     = (const float*)d_in[12];
    const float* alpha   = (const float*)d_in[13];
    const float* Wesa    = (const float*)d_in[14];
    const float* besa    = (const float*)d_in[15];
    const float* Wmu     = (const float*)d_in[16];
    const float* bmu     = (const float*)d_in[17];
    float* out = (float*)d_out;

    float *olfA, *olfB, *Ai, *Aj, *zx, *h0, *h1, *rlf, *lin, *mask;
    cudaGetSymbolAddress((void**)&olfA, g_olfA);
    cudaGetSymbolAddress((void**)&olfB, g_olfB);
    cudaGetSymbolAddress((void**)&Ai,   g_Ai);
    cudaGetSymbolAddress((void**)&Aj,   g_Aj);
    cudaGetSymbolAddress((void**)&zx,   g_zx);
    cudaGetSymbolAddress((void**)&h0,   g_h0);
    cudaGetSymbolAddress((void**)&h1,   g_h1);
    cudaGetSymbolAddress((void**)&rlf,  g_rlf);
    cudaGetSymbolAddress((void**)&lin,  g_lin);
    cudaGetSymbolAddress((void**)&mask, g_mask);
    float* hb[2] = {h0, h1};

    k_prep<<<NBS, 256>>>(centers, emb, counts, Wr);
    k_rlf0<<<NBSS, 256>>>(br);

    float* olf  = olfA;
    float* nolf = olfB;
    for (int l = 0; l < 3; l++) {
        // LSTM input projection: zx = olf @ W_ih^T     [7168 x 1024]
        sgemm128<0><<<dim3(NBS/BM, 1024/BN), 256>>>(olf, W_ih, 256, 0, zx, 1024, 256,
                                                    nullptr, nullptr, nullptr, nullptr, nullptr);
        // 28 recurrent steps
        for (int s = 0; s < SDIM; s++) {
            const float* hin = hb[(s+1) & 1];
            float* hout = hb[s & 1];
            k_lstm_step<<<dim3(8,8), 256>>>(zx, s, W_hh, b_ih, b_hh, nolf, hin, hout, s == 0);
        }
        // Ai = olf @ Wgr[:, :E]^T ; Aj = olf @ Wgr[:, E:2E]^T
        sgemm128<0><<<dim3(NBS/BM, ODIM/BN), 256>>>(olf, Wgr, 3*EDIM, 0, Ai, ODIM, 256,
                                                    nullptr, nullptr, nullptr, nullptr, nullptr);
        sgemm128<0><<<dim3(NBS/BM, ODIM/BN), 256>>>(olf, Wgr, 3*EDIM, EDIM, Aj, ODIM, 256,
                                                    nullptr, nullptr, nullptr, nullptr, nullptr);
        // rlf_lin = rlf @ Wgr3^T + Ai_i + Aj_j + bgr
        sgemm128<2><<<dim3(NBSS/BM, ODIM/BN), 256>>>(rlf, Wgr, 3*EDIM, 2*EDIM, lin, ODIM, 256,
                                                     Ai, Aj, bgr, nullptr, nullptr);
        // rlf = tanh(c0*lin + c1*(lin@Wbc^T + bbc)) * rel_mask
        sgemm128<3><<<dim3(NBSS/BM, ODIM/BN), 256>>>(lin, Wbc, 256, 0, rlf, ODIM, 256,
                                                     nullptr, nullptr, bbc, alpha, mask);
        float* tmp = olf; olf = nolf; nolf = tmp;
    }

    // F = rlf @ Wesa^T + besa   -> g_lin
    sgemm128<1><<<dim3(NBSS/BM, ODIM/BN), 256>>>(rlf, Wesa, 256, 0, lin, ODIM, 256,
                                                 besa, nullptr, nullptr, nullptr, nullptr);

    k_redF<<<NBS, 256>>>();
    k_gs<<<NBS, 256>>>(Wmu, bmu);
    k_redG<<<BDIM, 32>>>();
    k_final<<<NBS, 256>>>(out);
}

// round 7
// speedup vs baseline: 1.8789x; 1.8789x over previous
#include <cuda_runtime.h>
#include <math.h>

#define BDIM 256
#define SDIM 28
#define EDIM 256
#define ODIM 256
#define NBS  (BDIM*SDIM)          // 7168
#define NBSS (BDIM*SDIM*SDIM)     // 200704

// ---------------- scratch (device globals; no allocation allowed) -------------
__device__ float g_mask[NBS];
__device__ float g_u[NBS*EDIM];
__device__ float g_olfA[NBS*EDIM];
__device__ float g_olfB[NBS*EDIM];
__device__ float g_P[NBS*ODIM];
__device__ float g_XY[NBS*512];
__device__ float g_AiAj[NBS*512];
__device__ float g_zx[NBS*4*ODIM];
__device__ float g_h0[BDIM*ODIM];
__device__ float g_h1[BDIM*ODIM];
__device__ float g_c[BDIM*ODIM];
__device__ float g_Wc[3*256*256];     // composed weights (c0 I + c1 Wbc) @ Wgr_slice
__device__ float g_bias2[256];
__device__ float g_bvec[256];
__device__ float g_rlf[(size_t)NBSS*EDIM];   // 205 MB  (ping)
__device__ float g_lin[(size_t)NBSS*ODIM];   // 205 MB  (pong; final F lands here)
__device__ float g_gs[NBSS];
__device__ float g_M1[NBS*ODIM];
__device__ float g_D [NBS*ODIM];
__device__ float g_Mg[NBS];
__device__ float g_Dg[NBS];

// ---------------- prep: mask, u = (centers*mask)@Wr.T, olf0 -------------------
__global__ void k_prep(const float* __restrict__ centers, const float* __restrict__ emb,
                       const int* __restrict__ counts, const float* __restrict__ Wr) {
    int bs = blockIdx.x;           // b*S+s
    int e  = threadIdx.x;
    int b = bs / SDIM, s = bs % SDIM;
    float m = (s < counts[b]) ? 1.f : 0.f;
    if (e == 0) g_mask[bs] = m;
    float cx = centers[bs*3+0]*m, cy = centers[bs*3+1]*m, cz = centers[bs*3+2]*m;
    g_u[bs*EDIM+e]    = cx*Wr[e*3+0] + cy*Wr[e*3+1] + cz*Wr[e*3+2];
    g_olfA[bs*EDIM+e] = emb[bs*EDIM+e]*m;
}

// ---------------- weight composition ------------------------------------------
// Wc_z[n][k] = c0*Wgr[n, z*E+k] + c1 * sum_p Wbc[n][p] * Wgr[p, z*E+k]
__global__ void k_comb(const float* __restrict__ Wgr, const float* __restrict__ Wbc,
                       const float* __restrict__ alpha) {
    __shared__ float wb[256];
    int n = blockIdx.x, z = blockIdx.y, k = threadIdx.x;
    wb[k] = Wbc[n*256 + k];
    __syncthreads();
    float t = 1.f/(1.f + expf(-(*alpha)));
    float c0 = (1.f-t)*(1.f-t) + t*t;
    float c1 = 2.f*(1.f-t)*t;
    const float* G = Wgr + z*256;       // column slice, ld = 768
    float acc = 0.f;
    #pragma unroll 8
    for (int p = 0; p < 256; p++) acc += wb[p] * G[p*768 + k];
    g_Wc[(z*256 + n)*256 + k] = c0*G[n*768 + k] + c1*acc;
}

// bias2[o] = c0*bgr[o] + c1*dot(Wbc[o,:],bgr) + c1*bbc[o]
// bvec[o]  = dot(Wc3[o,:], br) + bias2[o]
__global__ void k_bias(const float* __restrict__ Wbc, const float* __restrict__ bgr,
                       const float* __restrict__ bbc, const float* __restrict__ br,
                       const float* __restrict__ alpha) {
    int o = threadIdx.x;
    float t = 1.f/(1.f + expf(-(*alpha)));
    float c0 = (1.f-t)*(1.f-t) + t*t;
    float c1 = 2.f*(1.f-t)*t;
    float d = 0.f;
    for (int p = 0; p < 256; p++) d += Wbc[o*256+p]*bgr[p];
    float b2 = c0*bgr[o] + c1*d + c1*bbc[o];
    const float* Wc3 = g_Wc + 2*256*256;
    float e = 0.f;
    for (int p = 0; p < 256; p++) e += Wc3[o*256+p]*br[p];
    g_bias2[o] = b2;
    g_bvec[o]  = e + b2;
}

// ---------------- unified fp32 SGEMM:  C = A @ W^T  (W row-major [N,K]) -------
// K == 256 always. 256 threads, 16x16 thread grid, TMxTN per thread.
// EPI 0: store
// EPI 1: +p3[col]                         (bias)
// EPI 2: stacked XY: col<256 -> +p1[row*256+col]+p3[col] ; else -> -p1[row*256+col-256]
// EPI 3: bez/tanh/mask: +p1[bi*512+col]+p2[jrow*512+256+col]+p3[col]; tanh; *m_i*m_j
template<int EPI, int BM_, int BN_, int BK_, int TM, int TN>
__global__ void __launch_bounds__(256)
sgemm(const float* __restrict__ A, const float* __restrict__ W,
      float* __restrict__ C, int ldc,
      const float* __restrict__ p1, const float* __restrict__ p2,
      const float* __restrict__ p3, const float* __restrict__ maskp) {
    __shared__ __align__(16) float As[BK_][BM_];
    __shared__ __align__(16) float Bs[BK_][BN_];
    const int K = 256;
    int bm = blockIdx.x * BM_;
    int bn = blockIdx.y * BN_;
    int tid = threadIdx.x;
    const int LC = BK_/4;
    int lr = tid / LC;
    int lc = (tid % LC) * 4;
    int tx = tid & 15, ty = tid >> 4;
    int rm = ty * TM, rn = tx * TN;
    float acc[TM][TN];
    #pragma unroll
    for (int i = 0; i < TM; i++)
        #pragma unroll
        for (int j = 0; j < TN; j++) acc[i][j] = 0.f;

    const float* Ap = A + (size_t)(bm+lr)*K + lc;
    const float* Wp = W + (size_t)(bn+lr)*K + lc;
    float4 av = *(const float4*)Ap;
    float4 bv = *(const float4*)Wp;

    for (int k0 = 0; k0 < K; k0 += BK_) {
        As[lc+0][lr]=av.x; As[lc+1][lr]=av.y; As[lc+2][lr]=av.z; As[lc+3][lr]=av.w;
        Bs[lc+0][lr]=bv.x; Bs[lc+1][lr]=bv.y; Bs[lc+2][lr]=bv.z; Bs[lc+3][lr]=bv.w;
        __syncthreads();
        if (k0 + BK_ < K) {
            av = *(const float4*)(Ap + k0 + BK_);
            bv = *(const float4*)(Wp + k0 + BK_);
        }
        #pragma unroll
        for (int k = 0; k < BK_; k++) {
            float a[TM], b[TN];
            #pragma unroll
            for (int i = 0; i < TM; i += 4) {
                float4 v = *(const float4*)&As[k][rm+i];
                a[i]=v.x; a[i+1]=v.y; a[i+2]=v.z; a[i+3]=v.w;
            }
            #pragma unroll
            for (int j = 0; j < TN; j += 4) {
                float4 v = *(const float4*)&Bs[k][rn+j];
                b[j]=v.x; b[j+1]=v.y; b[j+2]=v.z; b[j+3]=v.w;
            }
            #pragma unroll
            for (int i = 0; i < TM; i++)
                #pragma unroll
                for (int j = 0; j < TN; j++) acc[i][j] += a[i]*b[j];
        }
        __syncthreads();
    }

    #pragma unroll
    for (int i = 0; i < TM; i++) {
        int mrow = bm + rm + i;
        int bi = 0, jrow = 0; float mprod = 0.f;
        if (EPI == 3) {
            bi = mrow / SDIM;
            int b = mrow / (SDIM*SDIM);
            jrow = b*SDIM + (mrow % SDIM);
            mprod = maskp[bi]*maskp[jrow];
        }
        #pragma unroll
        for (int j = 0; j < TN; j++) {
            int col = bn + rn + j;
            float v = acc[i][j];
            if (EPI == 1) v += p3[col];
            if (EPI == 2) {
                int c2 = col & 255;
                float pv = p1[(size_t)mrow*256 + c2];
                v += (col < 256) ? (pv + p3[c2]) : (-pv);
            }
            if (EPI == 3) {
                v += p1[(size_t)bi*512 + col] + p2[(size_t)jrow*512 + 256 + col] + p3[col];
                v = tanhf(v) * mprod;
            }
            C[(size_t)mrow*ldc + col] = v;
        }
    }
}

// ---------------- layer-0 expansion: rlf = tanh(X_i + Y_j) * m_i m_j ----------
__global__ void k_expand() {
    int bi = blockIdx.x;               // b*S + i
    int o  = threadIdx.x;
    int b  = bi / SDIM;
    float x  = g_XY[(size_t)bi*512 + o];
    float mi = g_mask[bi];
    #pragma unroll 4
    for (int j = 0; j < SDIM; j++) {
        int bj = b*SDIM + j;
        float y = g_XY[(size_t)bj*512 + 256 + o];
        g_rlf[((size_t)bi*SDIM + j)*ODIM + o] = tanhf(x + y) * mi * g_mask[bj];
    }
}

// ---------------- LSTM recurrent step ----------------------------------------
__global__ void k_lstm_step(const float* __restrict__ zx, int step,
                            const float* __restrict__ Whh,
                            const float* __restrict__ bih, const float* __restrict__ bhh,
                            float* __restrict__ newolf,
                            const float* __restrict__ hin, float* __restrict__ hout,
                            int first) {
    __shared__ float sh[256][33];
    int tid = threadIdx.x;
    int u0 = blockIdx.x * 32;
    int b0 = blockIdx.y * 32;
    int lane = tid & 31, wid = tid >> 5;
    float acc[4][4];
    #pragma unroll
    for (int q=0;q<4;q++)
        #pragma unroll
        for (int g=0;g<4;g++) acc[q][g]=0.f;

    if (!first) {
        for (int m = 0; m < 32; m++) {
            int idx = m*256 + tid; int bl = idx >> 8, k = idx & 255;
            sh[k][bl] = hin[(b0+bl)*ODIM + k];
        }
        __syncthreads();
        int ub = u0 + wid*4;
        for (int k = 0; k < 256; k += 4) {
            float h0=sh[k][lane], h1=sh[k+1][lane], h2=sh[k+2][lane], h3=sh[k+3][lane];
            #pragma unroll
            for (int q=0;q<4;q++) {
                int u = ub + q;
                #pragma unroll
                for (int g=0; g<4; g++) {
                    const float4 w = *(const float4*)&Whh[(size_t)(g*ODIM+u)*ODIM + k];
                    acc[q][g] += w.x*h0 + w.y*h1 + w.z*h2 + w.w*h3;
                }
            }
        }
    }
    int b = b0 + lane;
    int zbase = (b*SDIM + step)*4*ODIM;
    float mk = g_mask[b*SDIM + step];
    #pragma unroll
    for (int q=0;q<4;q++) {
        int u = u0 + wid*4 + q;
        float zi = acc[q][0] + zx[zbase +          u] + bih[         u] + bhh[         u];
        float zf = acc[q][1] + zx[zbase + ODIM   + u] + bih[ODIM   + u] + bhh[ODIM   + u];
        float zg = acc[q][2] + zx[zbase + 2*ODIM + u] + bih[2*ODIM + u] + bhh[2*ODIM + u];
        float zo = acc[q][3] + zx[zbase + 3*ODIM + u] + bih[3*ODIM + u] + bhh[3*ODIM + u];
        float cold = first ? 0.f : g_c[b*ODIM+u];
        float si = 1.f/(1.f+expf(-zi));
        float sf = 1.f/(1.f+expf(-zf));
        float so = 1.f/(1.f+expf(-zo));
        float cn = sf*cold + si*tanhf(zg);
        float hn = so*tanhf(cn);
        g_c[b*ODIM+u] = cn;
        hout[b*ODIM+u] = hn;
        newolf[(b*SDIM+step)*ODIM + u] = hn*mk;
    }
}

// ---------------- attention readout -------------------------------------------
__global__ void k_redF() {
    int bj = blockIdx.x;               // b*S + j
    int b = bj / SDIM, j = bj % SDIM;
    int o = threadIdx.x;
    float fv[SDIM];
    float m1 = -1e30f;
    #pragma unroll
    for (int i = 0; i < SDIM; i++) {
        fv[i] = g_lin[((size_t)(b*SDIM+i)*SDIM + j)*ODIM + o];
        m1 = fmaxf(m1, fv[i]);
    }
    float d = 0.f;
    #pragma unroll
    for (int i = 0; i < SDIM; i++) d += expf(fv[i]-m1);
    g_M1[bj*ODIM+o] = m1;
    g_D [bj*ODIM+o] = d;
}

__global__ void k_gs(const float* __restrict__ Wmu, const float* __restrict__ bmu) {
    int bi = blockIdx.x;               // b*S + i
    int tid = threadIdx.x;
    int lane = tid & 31, w = tid >> 5;
    float wb[8];
    #pragma unroll
    for (int m = 0; m < 8; m++) {
        int o = lane + 32*m;
        wb[m] = (Wmu[o] + Wmu[ODIM+o] + Wmu[2*ODIM+o]) * (1.f/3.f);
    }
    float bbar = (bmu[0]+bmu[1]+bmu[2]) * (1.f/3.f);
    for (int j = w; j < SDIM; j += 8) {
        const float* F = &g_lin[((size_t)bi*SDIM + j)*ODIM];
        float p = 0.f;
        #pragma unroll
        for (int m = 0; m < 8; m++) p += F[lane + 32*m]*wb[m];
        #pragma unroll
        for (int off = 16; off; off >>= 1) p += __shfl_down_sync(0xffffffffu, p, off);
        if (lane == 0) g_gs[bi*SDIM + j] = p + bbar;
    }
}

__global__ void k_redG() {
    int b = blockIdx.x; int j = threadIdx.x;
    if (j >= SDIM) return;
    float vals[SDIM]; float m = -1e30f;
    #pragma unroll
    for (int i = 0; i < SDIM; i++) { vals[i] = g_gs[(b*SDIM+i)*SDIM+j]; m = fmaxf(m, vals[i]); }
    float d = 0.f;
    #pragma unroll
    for (int i = 0; i < SDIM; i++) d += expf(vals[i]-m);
    g_Mg[b*SDIM+j] = m;
    g_Dg[b*SDIM+j] = d;
}

__global__ void k_final(float* __restrict__ out) {
    int bi = blockIdx.x;               // b*S + i
    int o = threadIdx.x;
    int b = bi / SDIM;
    float acc = 0.f;
    for (int j = 0; j < SDIM; j++) {
        float fv = g_lin[((size_t)bi*SDIM + j)*ODIM + o];
        int bj = b*SDIM + j;
        float a1 = expf(fv - g_M1[bj*ODIM+o]) / g_D[bj*ODIM+o];
        float ag = expf(g_gs[bi*SDIM+j] - g_Mg[bj]) / g_Dg[bj];
        acc += 0.5f*(a1 + ag)*fv;
    }
    out[bi*ODIM+o] = acc * g_mask[bi];
}

// ---------------- host ---------------------------------------------------------
extern "C" void kernel_launch(void* const* d_in, const int* in_sizes, int n_in,
                              void* d_out, int out_size) {
    const float* centers = (const float*)d_in[0];
    const float* emb     = (const float*)d_in[1];
    const int*   counts  = (const int*)  d_in[2];
    const float* Wr      = (const float*)d_in[3];
    const float* br      = (const float*)d_in[4];
    const float* W_ih    = (const float*)d_in[5];
    const float* W_hh    = (const float*)d_in[6];
    const float* b_ih    = (const float*)d_in[7];
    const float* b_hh    = (const float*)d_in[8];
    const float* Wgr     = (const float*)d_in[9];
    const float* bgr     = (const float*)d_in[10];
    const float* Wbc     = (const float*)d_in[11];
    const float* bbc     = (const float*)d_in[12];
    const float* alpha   = (const float*)d_in[13];
    const float* Wesa    = (const float*)d_in[14];
    const float* besa    = (const float*)d_in[15];
    const float* Wmu     = (const float*)d_in[16];
    const float* bmu     = (const float*)d_in[17];
    float* out = (float*)d_out;

    float *olfA, *olfB, *P, *XY, *AiAj, *zx, *h0, *h1, *rlf, *lin, *mask, *Wc, *bias2, *bvec, *u;
    cudaGetSymbolAddress((void**)&olfA,  g_olfA);
    cudaGetSymbolAddress((void**)&olfB,  g_olfB);
    cudaGetSymbolAddress((void**)&P,     g_P);
    cudaGetSymbolAddress((void**)&XY,    g_XY);
    cudaGetSymbolAddress((void**)&AiAj,  g_AiAj);
    cudaGetSymbolAddress((void**)&zx,    g_zx);
    cudaGetSymbolAddress((void**)&h0,    g_h0);
    cudaGetSymbolAddress((void**)&h1,    g_h1);
    cudaGetSymbolAddress((void**)&rlf,   g_rlf);
    cudaGetSymbolAddress((void**)&lin,   g_lin);
    cudaGetSymbolAddress((void**)&mask,  g_mask);
    cudaGetSymbolAddress((void**)&Wc,    g_Wc);
    cudaGetSymbolAddress((void**)&bias2, g_bias2);
    cudaGetSymbolAddress((void**)&bvec,  g_bvec);
    cudaGetSymbolAddress((void**)&u,     g_u);
    const float* Wc3 = Wc + 2*256*256;
    float* hb[2] = {h0, h1};

    k_prep<<<NBS, 256>>>(centers, emb, counts, Wr);
    k_comb<<<dim3(256, 3), 256>>>(Wgr, Wbc, alpha);
    k_bias<<<1, 256>>>(Wbc, bgr, bbc, br, alpha);

    // ---- layer 0 (separable) ----
    // P = u @ Wc3^T
    sgemm<0,64,64,16,4,4><<<dim3(NBS/64, 4), 256>>>(u, Wc3, P, 256,
                                                    nullptr, nullptr, nullptr, nullptr);
    // XY: X = olf0@Wc1^T + P + bvec ; Y = olf0@Wc2^T - P   (stacked, N=512)
    sgemm<2,64,64,16,4,4><<<dim3(NBS/64, 8), 256>>>(olfA, Wc, XY, 512,
                                                    P, nullptr, bvec, nullptr);
    // rlf1 = tanh(X_i + Y_j) * m_i m_j
    k_expand<<<NBS, 256>>>();

    // ---- LSTM pass 0: olf1 = lstm(olf0) ----
    sgemm<0,128,128,8,8,8><<<dim3(NBS/128, 8), 256>>>(olfA, W_ih, zx, 1024,
                                                      nullptr, nullptr, nullptr, nullptr);
    for (int s = 0; s < SDIM; s++)
        k_lstm_step<<<dim3(8,8), 256>>>(zx, s, W_hh, b_ih, b_hh, olfB,
                                        hb[(s+1)&1], hb[s&1], s == 0);

    // ---- layer 1 ----
    sgemm<0,64,64,16,4,4><<<dim3(NBS/64, 8), 256>>>(olfB, Wc, AiAj, 512,
                                                    nullptr, nullptr, nullptr, nullptr);
    sgemm<3,128,128,8,8,8><<<dim3(NBSS/128, 2), 256>>>(rlf, Wc3, lin, 256,
                                                       AiAj, AiAj, bias2, mask);

    // ---- LSTM pass 1: olf2 = lstm(olf1) ----
    sgemm<0,128,128,8,8,8><<<dim3(NBS/128, 8), 256>>>(olfB, W_ih, zx, 1024,
                                                      nullptr, nullptr, nullptr, nullptr);
    for (int s = 0; s < SDIM; s++)
        k_lstm_step<<<dim3(8,8), 256>>>(zx, s, W_hh, b_ih, b_hh, olfA,
                                        hb[(s+1)&1], hb[s&1], s == 0);

    // ---- layer 2 ----
    sgemm<0,64,64,16,4,4><<<dim3(NBS/64, 8), 256>>>(olfA, Wc, AiAj, 512,
                                                    nullptr, nullptr, nullptr, nullptr);
    sgemm<3,128,128,8,8,8><<<dim3(NBSS/128, 2), 256>>>(lin, Wc3, rlf, 256,
                                                       AiAj, AiAj, bias2, mask);

    // ---- final: F = rlf @ Wesa^T + besa -> g_lin ----
    sgemm<1,128,128,8,8,8><<<dim3(NBSS/128, 2), 256>>>(rlf, Wesa, lin, 256,
                                                       nullptr, nullptr, besa, nullptr);

    k_redF<<<NBS, 256>>>();
    k_gs<<<NBS, 256>>>(Wmu, bmu);
    k_redG<<<BDIM, 32>>>();
    k_final<<<NBS, 256>>>(out);
}

// round 9
// speedup vs baseline: 2.3977x; 1.2761x over previous
#include <cuda_runtime.h>
#include <math.h>

#define BDIM 256
#define SDIM 28
#define EDIM 256
#define ODIM 256
#define NBS  (BDIM*SDIM)          // 7168
#define NBSS (BDIM*SDIM*SDIM)     // 200704

// ---------------- scratch (device globals; no allocation allowed) -------------
__device__ float g_mask[NBS];
__device__ float g_u[NBS*EDIM];
__device__ float g_olfA[NBS*EDIM];
__device__ float g_olfB[NBS*EDIM];
__device__ float g_P[NBS*ODIM];
__device__ float g_XY[NBS*512];
__device__ float g_AiAj[NBS*512];
__device__ float g_zx[NBS*4*ODIM];
__device__ float g_h0[BDIM*ODIM];
__device__ float g_h1[BDIM*ODIM];
__device__ float g_c[BDIM*ODIM];
__device__ float g_Wc[3*256*256];     // composed weights (c0 I + c1 Wbc) @ Wgr_slice
__device__ float g_bias2[256];
__device__ float g_bvec[256];
__device__ float g_rlf[(size_t)NBSS*EDIM];   // 205 MB  (ping)
__device__ float g_lin[(size_t)NBSS*ODIM];   // 205 MB  (pong; final F lands here)
__device__ float g_gs[NBSS];
__device__ float g_M1[NBS*ODIM];
__device__ float g_D [NBS*ODIM];
__device__ float g_Mg[NBS];
__device__ float g_Dg[NBS];

// ---------------- prep ---------------------------------------------------------
__global__ void k_prep(const float* __restrict__ centers, const float* __restrict__ emb,
                       const int* __restrict__ counts, const float* __restrict__ Wr) {
    int bs = blockIdx.x;           // b*S+s
    int e  = threadIdx.x;
    int b = bs / SDIM, s = bs % SDIM;
    float m = (s < counts[b]) ? 1.f : 0.f;
    if (e == 0) g_mask[bs] = m;
    float cx = centers[bs*3+0]*m, cy = centers[bs*3+1]*m, cz = centers[bs*3+2]*m;
    g_u[bs*EDIM+e]    = cx*Wr[e*3+0] + cy*Wr[e*3+1] + cz*Wr[e*3+2];
    g_olfA[bs*EDIM+e] = emb[bs*EDIM+e]*m;
}

// ---------------- weight composition ------------------------------------------
__global__ void k_comb(const float* __restrict__ Wgr, const float* __restrict__ Wbc,
                       const float* __restrict__ alpha) {
    __shared__ float wb[256];
    int n = blockIdx.x, z = blockIdx.y, k = threadIdx.x;
    wb[k] = Wbc[n*256 + k];
    __syncthreads();
    float t = 1.f/(1.f + expf(-(*alpha)));
    float c0 = (1.f-t)*(1.f-t) + t*t;
    float c1 = 2.f*(1.f-t)*t;
    const float* G = Wgr + z*256;       // column slice, ld = 768
    float acc = 0.f;
    #pragma unroll 8
    for (int p = 0; p < 256; p++) acc += wb[p] * G[p*768 + k];
    g_Wc[(z*256 + n)*256 + k] = c0*G[n*768 + k] + c1*acc;
}

__global__ void k_bias(const float* __restrict__ Wbc, const float* __restrict__ bgr,
                       const float* __restrict__ bbc, const float* __restrict__ br,
                       const float* __restrict__ alpha) {
    int o = threadIdx.x;
    float t = 1.f/(1.f + expf(-(*alpha)));
    float c0 = (1.f-t)*(1.f-t) + t*t;
    float c1 = 2.f*(1.f-t)*t;
    float d = 0.f;
    for (int p = 0; p < 256; p++) d += Wbc[o*256+p]*bgr[p];
    float b2 = c0*bgr[o] + c1*d + c1*bbc[o];
    const float* Wc3 = g_Wc + 2*256*256;
    float e = 0.f;
    for (int p = 0; p < 256; p++) e += Wc3[o*256+p]*br[p];
    g_bias2[o] = b2;
    g_bvec[o]  = e + b2;
}

// ---------------- tf32 tensor-core GEMM:  C = A @ W^T  -----------------------
// K == 256. 128x128 block tile, 8 warps of 64x32, mma.m16n8k8 tf32.
// EPI 0: store   1: +p3[col]
// EPI 3: bez/tanh/mask: +p1[bi*512+col] + p2[jrow*512+256+col] + p3[col]; tanh; *m_i*m_j
__device__ __forceinline__ unsigned f2t(float x) {
    unsigned u; asm("cvt.rna.tf32.f32 %0, %1;" : "=r"(u) : "f"(x)); return u;
}
__device__ __forceinline__ void mma8(float& c0, float& c1, float& c2, float& c3,
                                     unsigned a0, unsigned a1, unsigned a2, unsigned a3,
                                     unsigned b0, unsigned b1) {
    asm volatile("mma.sync.aligned.m16n8k8.row.col.f32.tf32.tf32.f32 "
                 "{%0,%1,%2,%3},{%4,%5,%6,%7},{%8,%9},{%0,%1,%2,%3};"
                 : "+f"(c0), "+f"(c1), "+f"(c2), "+f"(c3)
                 : "r"(a0), "r"(a1), "r"(a2), "r"(a3), "r"(b0), "r"(b1));
}

template<int EPI>
__global__ void __launch_bounds__(256, 1)
tgemm(const float* __restrict__ A, const float* __restrict__ W,
      float* __restrict__ C, int ldc,
      const float* __restrict__ p1, const float* __restrict__ p2,
      const float* __restrict__ p3, const float* __restrict__ maskp) {
    __shared__ unsigned As[128][36];   // [m][k], stride 36 -> conflict-free frag loads
    __shared__ unsigned Bs[128][36];   // [n][k]
    const int K = 256;
    int bm = blockIdx.x * 128;
    int bn = blockIdx.y * 128;
    int tid = threadIdx.x;
    int lane = tid & 31, w = tid >> 5;
    int wm = (w & 1) * 64, wn = (w >> 1) * 32;
    int g = lane >> 2, t = lane & 3;

    float acc[4][4][4];
    #pragma unroll
    for (int f = 0; f < 4; f++)
        #pragma unroll
        for (int n = 0; n < 4; n++)
            #pragma unroll
            for (int c = 0; c < 4; c++) acc[f][n][c] = 0.f;

    int lrow = tid >> 1;
    int lkh  = (tid & 1) << 4;         // 0 or 16
    const float4* Ag = (const float4*)(A + (size_t)(bm + lrow) * K + lkh);
    const float4* Wg = (const float4*)(W + (size_t)(bn + lrow) * K + lkh);
    float4 pa[4], pb[4];
    #pragma unroll
    for (int q = 0; q < 4; q++) { pa[q] = Ag[q]; pb[q] = Wg[q]; }

    for (int k0 = 0; k0 < K; k0 += 32) {
        #pragma unroll
        for (int q = 0; q < 4; q++) {
            uint4 ua = make_uint4(f2t(pa[q].x), f2t(pa[q].y), f2t(pa[q].z), f2t(pa[q].w));
            *(uint4*)&As[lrow][lkh + 4*q] = ua;
            uint4 ub = make_uint4(f2t(pb[q].x), f2t(pb[q].y), f2t(pb[q].z), f2t(pb[q].w));
            *(uint4*)&Bs[lrow][lkh + 4*q] = ub;
        }
        __syncthreads();
        if (k0 + 32 < K) {
            int off = (k0 + 32) >> 2;  // float4 units
            #pragma unroll
            for (int q = 0; q < 4; q++) { pa[q] = Ag[off + q]; pb[q] = Wg[off + q]; }
        }
        #pragma unroll
        for (int s = 0; s < 4; s++) {          // 4 mma k-steps x 8 = K-tile of 32
            unsigned af[4][4], bf[4][2];
            int kc = 8*s + t;
            #pragma unroll
            for (int f = 0; f < 4; f++) {
                int r = wm + 16*f + g;
                af[f][0] = As[r    ][kc];
                af[f][1] = As[r + 8][kc];
                af[f][2] = As[r    ][kc + 4];
                af[f][3] = As[r + 8][kc + 4];
            }
            #pragma unroll
            for (int n = 0; n < 4; n++) {
                int cn = wn + 8*n + g;
                bf[n][0] = Bs[cn][kc];
                bf[n][1] = Bs[cn][kc + 4];
            }
            #pragma unroll
            for (int f = 0; f < 4; f++)
                #pragma unroll
                for (int n = 0; n < 4; n++)
                    mma8(acc[f][n][0], acc[f][n][1], acc[f][n][2], acc[f][n][3],
                         af[f][0], af[f][1], af[f][2], af[f][3], bf[n][0], bf[n][1]);
        }
        __syncthreads();
    }

    // ---- epilogue: thread owns rows {g, g+8} per m-frag, cols {2t,2t+1}+8n+wn
    #pragma unroll
    for (int f = 0; f < 4; f++) {
        #pragma unroll
        for (int half = 0; half < 2; half++) {
            int mrow = bm + wm + 16*f + g + 8*half;
            int bi = 0, jrow = 0; float mprod = 0.f;
            if (EPI == 3) {
                bi = mrow / SDIM;
                int b = mrow / (SDIM*SDIM);
                jrow = b*SDIM + (mrow % SDIM);
                mprod = maskp[bi]*maskp[jrow];
            }
            #pragma unroll
            for (int n = 0; n < 4; n++) {
                int col = bn + wn + 8*n + 2*t;
                float v0 = acc[f][n][half ? 2 : 0];
                float v1 = acc[f][n][half ? 3 : 1];
                if (EPI == 1) { v0 += p3[col]; v1 += p3[col + 1]; }
                if (EPI == 3) {
                    v0 += p1[(size_t)bi*512 + col]     + p2[(size_t)jrow*512 + 256 + col]     + p3[col];
                    v1 += p1[(size_t)bi*512 + col + 1] + p2[(size_t)jrow*512 + 256 + col + 1] + p3[col + 1];
                    v0 = tanhf(v0) * mprod;
                    v1 = tanhf(v1) * mprod;
                }
                *(float2*)&C[(size_t)mrow*ldc + col] = make_float2(v0, v1);
            }
        }
    }
}

// ---------------- small SIMT SGEMM (64x64 tiles) for P / XY -------------------
// EPI 0: store
// EPI 2: stacked XY: col<256 -> +p1[row*256+col]+p3[col] ; else -> -p1[row*256+col-256]
template<int EPI>
__global__ void __launch_bounds__(256)
sgemm64(const float* __restrict__ A, const float* __restrict__ W,
        float* __restrict__ C, int ldc,
        const float* __restrict__ p1, const float* __restrict__ p3) {
    __shared__ __align__(16) float As[16][64];
    __shared__ __align__(16) float Bs[16][64];
    const int K = 256;
    int bm = blockIdx.x * 64;
    int bn = blockIdx.y * 64;
    int tid = threadIdx.x;
    int lr = tid / 4;
    int lc = (tid % 4) * 4;
    int tx = tid & 15, ty = tid >> 4;
    int rm = ty * 4, rn = tx * 4;
    float acc[4][4];
    #pragma unroll
    for (int i = 0; i < 4; i++)
        #pragma unroll
        for (int j = 0; j < 4; j++) acc[i][j] = 0.f;

    const float* Ap = A + (size_t)(bm+lr)*K + lc;
    const float* Wp = W + (size_t)(bn+lr)*K + lc;
    float4 av = *(const float4*)Ap;
    float4 bv = *(const float4*)Wp;

    for (int k0 = 0; k0 < K; k0 += 16) {
        As[lc+0][lr]=av.x; As[lc+1][lr]=av.y; As[lc+2][lr]=av.z; As[lc+3][lr]=av.w;
        Bs[lc+0][lr]=bv.x; Bs[lc+1][lr]=bv.y; Bs[lc+2][lr]=bv.z; Bs[lc+3][lr]=bv.w;
        __syncthreads();
        if (k0 + 16 < K) {
            av = *(const float4*)(Ap + k0 + 16);
            bv = *(const float4*)(Wp + k0 + 16);
        }
        #pragma unroll
        for (int k = 0; k < 16; k++) {
            float4 a0 = *(const float4*)&As[k][rm];
            float4 b0 = *(const float4*)&Bs[k][rn];
            float a[4] = {a0.x,a0.y,a0.z,a0.w};
            float bb[4] = {b0.x,b0.y,b0.z,b0.w};
            #pragma unroll
            for (int i = 0; i < 4; i++)
                #pragma unroll
                for (int j = 0; j < 4; j++) acc[i][j] += a[i]*bb[j];
        }
        __syncthreads();
    }

    #pragma unroll
    for (int i = 0; i < 4; i++) {
        int mrow = bm + rm + i;
        #pragma unroll
        for (int j = 0; j < 4; j++) {
            int col = bn + rn + j;
            float v = acc[i][j];
            if (EPI == 2) {
                int c2 = col & 255;
                float pv = p1[(size_t)mrow*256 + c2];
                v += (col < 256) ? (pv + p3[c2]) : (-pv);
            }
            C[(size_t)mrow*ldc + col] = v;
        }
    }
}

// ---------------- layer-0 expansion: rlf = tanh(X_i + Y_j) * m_i m_j ----------
__global__ void k_expand() {
    int bi = blockIdx.x;               // b*S + i
    int o  = threadIdx.x;
    int b  = bi / SDIM;
    float x  = g_XY[(size_t)bi*512 + o];
    float mi = g_mask[bi];
    #pragma unroll 4
    for (int j = 0; j < SDIM; j++) {
        int bj = b*SDIM + j;
        float y = g_XY[(size_t)bj*512 + 256 + o];
        g_rlf[((size_t)bi*SDIM + j)*ODIM + o] = tanhf(x + y) * mi * g_mask[bj];
    }
}

// ---------------- LSTM recurrent step ----------------------------------------
__global__ void k_lstm_step(const float* __restrict__ zx, int step,
                            const float* __restrict__ Whh,
                            const float* __restrict__ bih, const float* __restrict__ bhh,
                            float* __restrict__ newolf,
                            const float* __restrict__ hin, float* __restrict__ hout,
                            int first) {
    __shared__ float sh[256][33];
    int tid = threadIdx.x;
    int u0 = blockIdx.x * 32;
    int b0 = blockIdx.y * 32;
    int lane = tid & 31, wid = tid >> 5;
    float acc[4][4];
    #pragma unroll
    for (int q=0;q<4;q++)
        #pragma unroll
        for (int g=0;g<4;g++) acc[q][g]=0.f;

    if (!first) {
        for (int m = 0; m < 32; m++) {
            int idx = m*256 + tid; int bl = idx >> 8, k = idx & 255;
            sh[k][bl] = hin[(b0+bl)*ODIM + k];
        }
        __syncthreads();
        int ub = u0 + wid*4;
        for (int k = 0; k < 256; k += 4) {
            float h0=sh[k][lane], h1=sh[k+1][lane], h2=sh[k+2][lane], h3=sh[k+3][lane];
            #pragma unroll
            for (int q=0;q<4;q++) {
                int u = ub + q;
                #pragma unroll
                for (int g=0; g<4; g++) {
                    const float4 w = *(const float4*)&Whh[(size_t)(g*ODIM+u)*ODIM + k];
                    acc[q][g] += w.x*h0 + w.y*h1 + w.z*h2 + w.w*h3;
                }
            }
        }
    }
    int b = b0 + lane;
    int zbase = (b*SDIM + step)*4*ODIM;
    float mk = g_mask[b*SDIM + step];
    #pragma unroll
    for (int q=0;q<4;q++) {
        int u = u0 + wid*4 + q;
        float zi = acc[q][0] + zx[zbase +          u] + bih[         u] + bhh[         u];
        float zf = acc[q][1] + zx[zbase + ODIM   + u] + bih[ODIM   + u] + bhh[ODIM   + u];
        float zg = acc[q][2] + zx[zbase + 2*ODIM + u] + bih[2*ODIM + u] + bhh[2*ODIM + u];
        float zo = acc[q][3] + zx[zbase + 3*ODIM + u] + bih[3*ODIM + u] + bhh[3*ODIM + u];
        float cold = first ? 0.f : g_c[b*ODIM+u];
        float si = 1.f/(1.f+expf(-zi));
        float sf = 1.f/(1.f+expf(-zf));
        float so = 1.f/(1.f+expf(-zo));
        float cn = sf*cold + si*tanhf(zg);
        float hn = so*tanhf(cn);
        g_c[b*ODIM+u] = cn;
        hout[b*ODIM+u] = hn;
        newolf[(b*SDIM+step)*ODIM + u] = hn*mk;
    }
}

// ---------------- attention readout -------------------------------------------
__global__ void k_redF() {
    int bj = blockIdx.x;               // b*S + j
    int b = bj / SDIM, j = bj % SDIM;
    int o = threadIdx.x;
    float fv[SDIM];
    float m1 = -1e30f;
    #pragma unroll
    for (int i = 0; i < SDIM; i++) {
        fv[i] = g_lin[((size_t)(b*SDIM+i)*SDIM + j)*ODIM + o];
        m1 = fmaxf(m1, fv[i]);
    }
    float d = 0.f;
    #pragma unroll
    for (int i = 0; i < SDIM; i++) d += expf(fv[i]-m1);
    g_M1[bj*ODIM+o] = m1;
    g_D [bj*ODIM+o] = d;
}

__global__ void k_gs(const float* __restrict__ Wmu, const float* __restrict__ bmu) {
    int bi = blockIdx.x;               // b*S + i
    int tid = threadIdx.x;
    int lane = tid & 31, w = tid >> 5;
    float wb[8];
    #pragma unroll
    for (int m = 0; m < 8; m++) {
        int o = lane + 32*m;
        wb[m] = (Wmu[o] + Wmu[ODIM+o] + Wmu[2*ODIM+o]) * (1.f/3.f);
    }
    float bbar = (bmu[0]+bmu[1]+bmu[2]) * (1.f/3.f);
    for (int j = w; j < SDIM; j += 8) {
        const float* F = &g_lin[((size_t)bi*SDIM + j)*ODIM];
        float p = 0.f;
        #pragma unroll
        for (int m = 0; m < 8; m++) p += F[lane + 32*m]*wb[m];
        #pragma unroll
        for (int off = 16; off; off >>= 1) p += __shfl_down_sync(0xffffffffu, p, off);
        if (lane == 0) g_gs[bi*SDIM + j] = p + bbar;
    }
}

__global__ void k_redG() {
    int b = blockIdx.x; int j = threadIdx.x;
    if (j >= SDIM) return;
    float vals[SDIM]; float m = -1e30f;
    #pragma unroll
    for (int i = 0; i < SDIM; i++) { vals[i] = g_gs[(b*SDIM+i)*SDIM+j]; m = fmaxf(m, vals[i]); }
    float d = 0.f;
    #pragma unroll
    for (int i = 0; i < SDIM; i++) d += expf(vals[i]-m);
    g_Mg[b*SDIM+j] = m;
    g_Dg[b*SDIM+j] = d;
}

__global__ void k_final(float* __restrict__ out) {
    int bi = blockIdx.x;               // b*S + i
    int o = threadIdx.x;
    int b = bi / SDIM;
    float acc = 0.f;
    for (int j = 0; j < SDIM; j++) {
        float fv = g_lin[((size_t)bi*SDIM + j)*ODIM + o];
        int bj = b*SDIM + j;
        float a1 = expf(fv - g_M1[bj*ODIM+o]) / g_D[bj*ODIM+o];
        float ag = expf(g_gs[bi*SDIM+j] - g_Mg[bj]) / g_Dg[bj];
        acc += 0.5f*(a1 + ag)*fv;
    }
    out[bi*ODIM+o] = acc * g_mask[bi];
}

// ---------------- host ---------------------------------------------------------
extern "C" void kernel_launch(void* const* d_in, const int* in_sizes, int n_in,
                              void* d_out, int out_size) {
    const float* centers = (const float*)d_in[0];
    const float* emb     = (const float*)d_in[1];
    const int*   counts  = (const int*)  d_in[2];
    const float* Wr      = (const float*)d_in[3];
    const float* br      = (const float*)d_in[4];
    const float* W_ih    = (const float*)d_in[5];
    const float* W_hh    = (const float*)d_in[6];
    const float* b_ih    = (const float*)d_in[7];
    const float* b_hh    = (const float*)d_in[8];
    const float* Wgr     = (const float*)d_in[9];
    const float* bgr     = (const float*)d_in[10];
    const float* Wbc     = (const float*)d_in[11];
    const float* bbc     = (const float*)d_in[12];
    const float* alpha   = (const float*)d_in[13];
    const float* Wesa    = (const float*)d_in[14];
    const float* besa    = (const float*)d_in[15];
    const float* Wmu     = (const float*)d_in[16];
    const float* bmu     = (const float*)d_in[17];
    float* out = (float*)d_out;

    float *olfA, *olfB, *P, *XY, *AiAj, *zx, *h0, *h1, *rlf, *lin, *mask, *Wc, *bias2, *bvec, *u;
    cudaGetSymbolAddress((void**)&olfA,  g_olfA);
    cudaGetSymbolAddress((void**)&olfB,  g_olfB);
    cudaGetSymbolAddress((void**)&P,     g_P);
    cudaGetSymbolAddress((void**)&XY,    g_XY);
    cudaGetSymbolAddress((void**)&AiAj,  g_AiAj);
    cudaGetSymbolAddress((void**)&zx,    g_zx);
    cudaGetSymbolAddress((void**)&h0,    g_h0);
    cudaGetSymbolAddress((void**)&h1,    g_h1);
    cudaGetSymbolAddress((void**)&rlf,   g_rlf);
    cudaGetSymbolAddress((void**)&lin,   g_lin);
    cudaGetSymbolAddress((void**)&mask,  g_mask);
    cudaGetSymbolAddress((void**)&Wc,    g_Wc);
    cudaGetSymbolAddress((void**)&bias2, g_bias2);
    cudaGetSymbolAddress((void**)&bvec,  g_bvec);
    cudaGetSymbolAddress((void**)&u,     g_u);
    const float* Wc3 = Wc + 2*256*256;
    float* hb[2] = {h0, h1};

    k_prep<<<NBS, 256>>>(centers, emb, counts, Wr);
    k_comb<<<dim3(256, 3), 256>>>(Wgr, Wbc, alpha);
    k_bias<<<1, 256>>>(Wbc, bgr, bbc, br, alpha);

    // ---- layer 0 (separable) ----
    // P = u @ Wc3^T
    sgemm64<0><<<dim3(NBS/64, 4), 256>>>(u, Wc3, P, 256, nullptr, nullptr);
    // XY: X = olf0@Wc1^T + P + bvec ; Y = olf0@Wc2^T - P   (stacked, N=512)
    sgemm64<2><<<dim3(NBS/64, 8), 256>>>(olfA, Wc, XY, 512, P, bvec);
    // rlf1 = tanh(X_i + Y_j) * m_i m_j
    k_expand<<<NBS, 256>>>();

    // ---- LSTM pass 0: olf1 = lstm(olf0) ----
    tgemm<0><<<dim3(NBS/128, 8), 256>>>(olfA, W_ih, zx, 1024,
                                        nullptr, nullptr, nullptr, nullptr);
    for (int s = 0; s < SDIM; s++)
        k_lstm_step<<<dim3(8,8), 256>>>(zx, s, W_hh, b_ih, b_hh, olfB,
                                        hb[(s+1)&1], hb[s&1], s == 0);

    // ---- layer 1 ----
    tgemm<0><<<dim3(NBS/128, 4), 256>>>(olfB, Wc, AiAj, 512,
                                        nullptr, nullptr, nullptr, nullptr);
    tgemm<3><<<dim3(NBSS/128, 2), 256>>>(rlf, Wc3, lin, 256,
                                         AiAj, AiAj, bias2, mask);

    // ---- LSTM pass 1: olf2 = lstm(olf1) ----
    tgemm<0><<<dim3(NBS/128, 8), 256>>>(olfB, W_ih, zx, 1024,
                                        nullptr, nullptr, nullptr, nullptr);
    for (int s = 0; s < SDIM; s++)
        k_lstm_step<<<dim3(8,8), 256>>>(zx, s, W_hh, b_ih, b_hh, olfA,
                                        hb[(s+1)&1], hb[s&1], s == 0);

    // ---- layer 2 ----
    tgemm<0><<<dim3(NBS/128, 4), 256>>>(olfA, Wc, AiAj, 512,
                                        nullptr, nullptr, nullptr, nullptr);
    tgemm<3><<<dim3(NBSS/128, 2), 256>>>(lin, Wc3, rlf, 256,
                                         AiAj, AiAj, bias2, mask);

    // ---- final: F = rlf @ Wesa^T + besa -> g_lin ----
    tgemm<1><<<dim3(NBSS/128, 2), 256>>>(rlf, Wesa, lin, 256,
                                         nullptr, nullptr, besa, nullptr);

    k_redF<<<NBS, 256>>>();
    k_gs<<<NBS, 256>>>(Wmu, bmu);
    k_redG<<<BDIM, 32>>>();
    k_final<<<NBS, 256>>>(out);
}